// round 2
// baseline (speedup 1.0000x reference)
#include <cuda_runtime.h>
#include <math.h>

#define B_ 8
#define S_ 1024
#define H_ 16
#define D_ 64
#define M_ 1024

#define TILE 64
#define THREADS 256
#define STRIDE 68  // padded smem row stride (floats): 68%32=4 -> conflict-free row-varying access

__device__ unsigned char g_rowmask[B_ * S_];
__device__ unsigned char g_colmask[B_ * S_];

__global__ void zero_masks_kernel() {
    int i = blockIdx.x * blockDim.x + threadIdx.x;
    if (i < B_ * S_) {
        g_rowmask[i] = 0;
        g_colmask[i] = 0;
    }
}

__global__ void scatter_masks_kernel(const int* __restrict__ qm_b, const int* __restrict__ qm_s,
                                     const int* __restrict__ km_b, const int* __restrict__ km_s) {
    int i = blockIdx.x * blockDim.x + threadIdx.x;
    if (i < M_) {
        g_rowmask[qm_b[i] * S_ + qm_s[i]] = 1;
        g_colmask[km_b[i] * S_ + km_s[i]] = 1;
    }
}

// Flash-attention style fused kernel.
// Grid: B*H*(S/TILE) CTAs; 256 threads.
// Thread t owns q-row r = t/4 and segment sub = t%4 (16 k-cols in QK phase, 16 d-cols in PV phase).
__global__ __launch_bounds__(THREADS) void attn_kernel(const float* __restrict__ Q,
                                                       const float* __restrict__ K,
                                                       const float* __restrict__ V,
                                                       float* __restrict__ O) {
    extern __shared__ float smem[];
    float* Qs = smem;                 // TILE * STRIDE
    float* Ks = Qs + TILE * STRIDE;   // TILE * STRIDE  (aliased as Ps after QK phase)
    float* Vs = Ks + TILE * STRIDE;   // TILE * 64 (unpadded; within-row access only)
    int*   Cm = (int*)(Vs + TILE * 64);  // 64 col-mask flags
    float* Ps = Ks;                   // alias

    const int cta = blockIdx.x;
    const int qt = cta & (S_ / TILE - 1);
    const int h = (cta / (S_ / TILE)) & (H_ - 1);
    const int b = cta / (S_ / TILE * H_);
    const int tid = threadIdx.x;
    const int r = tid >> 2;
    const int sub = tid & 3;
    const int kb = sub * 16;
    const int db = sub * 16;

    // ---- load Q tile (rows strided by H*D in gmem) ----
    const float* Qbase = Q + ((size_t)b * S_ + (size_t)qt * TILE) * (H_ * D_) + h * D_;
    #pragma unroll
    for (int i = tid; i < TILE * 16; i += THREADS) {
        int rr = i >> 4, c4 = i & 15;
        float4 v = *reinterpret_cast<const float4*>(Qbase + (size_t)rr * (H_ * D_) + c4 * 4);
        *reinterpret_cast<float4*>(&Qs[rr * STRIDE + c4 * 4]) = v;
    }

    const int rmask = g_rowmask[b * S_ + qt * TILE + r];

    float m = -INFINITY;
    float l = 0.0f;
    float oacc[16];
    #pragma unroll
    for (int i = 0; i < 16; ++i) oacc[i] = 0.0f;

    const float* Kslab = K + (size_t)b * S_ * (H_ * D_) + h * D_;
    const float* Vslab = V + ((size_t)b * H_ + h) * S_ * D_;

    for (int kt = 0; kt < S_ / TILE; ++kt) {
        __syncthreads();  // previous tile fully consumed (incl. Ps read)

        // ---- load K tile ----
        const float* Kbase = Kslab + (size_t)kt * TILE * (H_ * D_);
        #pragma unroll
        for (int i = tid; i < TILE * 16; i += THREADS) {
            int rr = i >> 4, c4 = i & 15;
            float4 v = *reinterpret_cast<const float4*>(Kbase + (size_t)rr * (H_ * D_) + c4 * 4);
            *reinterpret_cast<float4*>(&Ks[rr * STRIDE + c4 * 4]) = v;
        }
        // ---- load V tile (fully contiguous 64*64) ----
        const float* Vbase = Vslab + (size_t)kt * TILE * D_;
        #pragma unroll
        for (int i = tid; i < TILE * 16; i += THREADS) {
            float4 v = *reinterpret_cast<const float4*>(Vbase + i * 4);
            *reinterpret_cast<float4*>(&Vs[i * 4]) = v;
        }
        if (tid < TILE) Cm[tid] = g_colmask[b * S_ + kt * TILE + tid];
        __syncthreads();

        // ---- S = Q K^T for this thread's 16 k-cols ----
        float sv[16];
        #pragma unroll
        for (int kk = 0; kk < 16; ++kk) sv[kk] = 0.0f;
        #pragma unroll
        for (int d4 = 0; d4 < 16; ++d4) {
            float4 q4 = *reinterpret_cast<const float4*>(&Qs[r * STRIDE + d4 * 4]);
            #pragma unroll
            for (int kk = 0; kk < 16; ++kk) {
                float4 k4 = *reinterpret_cast<const float4*>(&Ks[(kb + kk) * STRIDE + d4 * 4]);
                sv[kk] += q4.x * k4.x + q4.y * k4.y + q4.z * k4.z + q4.w * k4.w;
            }
        }

        // ---- mask + online softmax ----
        float tmax = -INFINITY;
        #pragma unroll
        for (int kk = 0; kk < 16; ++kk) {
            float x = sv[kk] * 0.125f;  // 1/sqrt(64)
            if (rmask || Cm[kb + kk]) x = -1e10f;
            sv[kk] = x;
            tmax = fmaxf(tmax, x);
        }
        tmax = fmaxf(tmax, __shfl_xor_sync(0xffffffffu, tmax, 1));
        tmax = fmaxf(tmax, __shfl_xor_sync(0xffffffffu, tmax, 2));
        float mnew = fmaxf(m, tmax);
        float alpha = __expf(m - mnew);
        float psum = 0.0f;
        #pragma unroll
        for (int kk = 0; kk < 16; ++kk) {
            float p = __expf(sv[kk] - mnew);
            sv[kk] = p;
            psum += p;
        }
        psum += __shfl_xor_sync(0xffffffffu, psum, 1);
        psum += __shfl_xor_sync(0xffffffffu, psum, 2);
        l = l * alpha + psum;
        m = mnew;
        #pragma unroll
        for (int i = 0; i < 16; ++i) oacc[i] *= alpha;

        __syncthreads();  // everyone done reading Ks before Ps overwrites it

        #pragma unroll
        for (int g = 0; g < 4; ++g) {
            float4 pv = make_float4(sv[g * 4 + 0], sv[g * 4 + 1], sv[g * 4 + 2], sv[g * 4 + 3]);
            *reinterpret_cast<float4*>(&Ps[r * STRIDE + kb + g * 4]) = pv;
        }
        __syncthreads();  // Ps visible

        // ---- O += P V ----
        #pragma unroll 4
        for (int k = 0; k < TILE; ++k) {
            float p = Ps[r * STRIDE + k];
            const float4* vp = reinterpret_cast<const float4*>(&Vs[k * 64 + db]);
            float4 v0 = vp[0], v1 = vp[1], v2 = vp[2], v3 = vp[3];
            oacc[0]  += p * v0.x; oacc[1]  += p * v0.y; oacc[2]  += p * v0.z; oacc[3]  += p * v0.w;
            oacc[4]  += p * v1.x; oacc[5]  += p * v1.y; oacc[6]  += p * v1.z; oacc[7]  += p * v1.w;
            oacc[8]  += p * v2.x; oacc[9]  += p * v2.y; oacc[10] += p * v2.z; oacc[11] += p * v2.w;
            oacc[12] += p * v3.x; oacc[13] += p * v3.y; oacc[14] += p * v3.z; oacc[15] += p * v3.w;
        }
    }

    // ---- epilogue: normalize + store (O is (B,H,S,D)) ----
    const float inv = 1.0f / l;
    float* ob = O + (((size_t)b * H_ + h) * S_ + (size_t)qt * TILE + r) * D_ + db;
    #pragma unroll
    for (int g = 0; g < 4; ++g) {
        float4 o = make_float4(oacc[g * 4 + 0] * inv, oacc[g * 4 + 1] * inv,
                               oacc[g * 4 + 2] * inv, oacc[g * 4 + 3] * inv);
        *reinterpret_cast<float4*>(&ob[g * 4]) = o;
    }
}

static const int SMEM_BYTES = (TILE * STRIDE * 2 + TILE * 64 + 64) * 4;  // 51456

extern "C" void kernel_launch(void* const* d_in, const int* in_sizes, int n_in,
                              void* d_out, int out_size) {
    const float* Q = (const float*)d_in[0];
    const float* K = (const float*)d_in[1];
    const float* V = (const float*)d_in[2];
    const int* qm_b = (const int*)d_in[3];
    const int* qm_s = (const int*)d_in[4];
    const int* km_b = (const int*)d_in[5];
    const int* km_s = (const int*)d_in[6];
    float* O = (float*)d_out;

    cudaFuncSetAttribute(attn_kernel, cudaFuncAttributeMaxDynamicSharedMemorySize, SMEM_BYTES);

    zero_masks_kernel<<<(B_ * S_ + 255) / 256, 256>>>();
    scatter_masks_kernel<<<(M_ + 255) / 256, 256>>>(qm_b, qm_s, km_b, km_s);
    attn_kernel<<<B_ * H_ * (S_ / TILE), THREADS, SMEM_BYTES>>>(Q, K, V, O);
}

// round 6
// speedup vs baseline: 6.4164x; 6.4164x over previous
#include <cuda_runtime.h>
#include <math.h>

#define B_ 8
#define S_ 1024
#define H_ 16
#define D_ 64
#define M_ 1024

#define TILE 64
#define THREADS 256
#define STRIDE 68  // padded row stride (floats); 16B-aligned rows

__device__ unsigned char g_rowmask[B_ * S_];
__device__ unsigned char g_colmask[B_ * S_];

__global__ void zero_masks_kernel() {
    int i = blockIdx.x * blockDim.x + threadIdx.x;
    if (i < B_ * S_) {
        g_rowmask[i] = 0;
        g_colmask[i] = 0;
    }
}

__global__ void scatter_masks_kernel(const int* __restrict__ qm_b, const int* __restrict__ qm_s,
                                     const int* __restrict__ km_b, const int* __restrict__ km_s) {
    int i = blockIdx.x * blockDim.x + threadIdx.x;
    if (i < M_) {
        g_rowmask[qm_b[i] * S_ + qm_s[i]] = 1;
        g_colmask[km_b[i] * S_ + km_s[i]] = 1;
    }
}

// Flash-attention, 4x4 register-blocked.
// Thread (tx=tid&15, ty=tid>>4): rows R = 4*ty+{0..3}.
// QK phase cols: scattered {tx, tx+16, tx+32, tx+48} (2-way max bank conflict).
// PV phase d-cols: contiguous {4*tx..4*tx+3} (vectorized V loads, coalesced O stores).
__global__ __launch_bounds__(THREADS, 2) void attn_kernel(const float* __restrict__ Q,
                                                          const float* __restrict__ K,
                                                          const float* __restrict__ V,
                                                          float* __restrict__ O) {
    extern __shared__ float smem[];
    float* Qs = smem;                  // 64 * STRIDE
    float* Ks = Qs + TILE * STRIDE;    // 64 * STRIDE  (aliased by Ps)
    float* Vs = Ks + TILE * STRIDE;    // 64 * STRIDE
    int*   Cm = (int*)(Vs + TILE * STRIDE);  // 64 col-mask flags
    float* Ps = Ks;

    const int cta = blockIdx.x;
    const int qt = cta & (S_ / TILE - 1);
    const int h  = (cta / (S_ / TILE)) & (H_ - 1);
    const int b  = cta / (S_ / TILE * H_);
    const int tid = threadIdx.x;
    const int tx = tid & 15;
    const int ty = tid >> 4;

    // ---- load Q tile, folding softmax scale (1/8) in ----
    const float* Qbase = Q + ((size_t)b * S_ + (size_t)qt * TILE) * (H_ * D_) + h * D_;
    #pragma unroll
    for (int i = tid; i < TILE * 16; i += THREADS) {
        int rr = i >> 4, c4 = i & 15;
        float4 v = *reinterpret_cast<const float4*>(Qbase + (size_t)rr * (H_ * D_) + c4 * 4);
        v.x *= 0.125f; v.y *= 0.125f; v.z *= 0.125f; v.w *= 0.125f;
        *reinterpret_cast<float4*>(&Qs[rr * STRIDE + c4 * 4]) = v;
    }

    int rm[4];
    #pragma unroll
    for (int j = 0; j < 4; ++j) rm[j] = g_rowmask[b * S_ + qt * TILE + 4 * ty + j];

    float m_[4], l_[4];
    float oacc[4][4];
    #pragma unroll
    for (int j = 0; j < 4; ++j) {
        m_[j] = -INFINITY; l_[j] = 0.0f;
        #pragma unroll
        for (int c = 0; c < 4; ++c) oacc[j][c] = 0.0f;
    }

    const float* Kslab = K + (size_t)b * S_ * (H_ * D_) + h * D_;
    const float* Vslab = V + ((size_t)b * H_ + h) * S_ * D_;

    for (int kt = 0; kt < S_ / TILE; ++kt) {
        __syncthreads();  // prev tile fully consumed (Vs + Ps reads done)

        // ---- load K tile (rows strided in gmem) ----
        const float* Kbase = Kslab + (size_t)kt * TILE * (H_ * D_);
        #pragma unroll
        for (int i = tid; i < TILE * 16; i += THREADS) {
            int rr = i >> 4, c4 = i & 15;
            float4 v = *reinterpret_cast<const float4*>(Kbase + (size_t)rr * (H_ * D_) + c4 * 4);
            *reinterpret_cast<float4*>(&Ks[rr * STRIDE + c4 * 4]) = v;
        }
        // ---- load V tile (contiguous in gmem) ----
        const float* Vbase = Vslab + (size_t)kt * TILE * D_;
        #pragma unroll
        for (int i = tid; i < TILE * 16; i += THREADS) {
            int rr = i >> 4, c4 = i & 15;
            float4 v = *reinterpret_cast<const float4*>(Vbase + i * 4);
            *reinterpret_cast<float4*>(&Vs[rr * STRIDE + c4 * 4]) = v;
        }
        if (tid < TILE) Cm[tid] = g_colmask[b * S_ + kt * TILE + tid];
        __syncthreads();

        int cm[4];
        #pragma unroll
        for (int i = 0; i < 4; ++i) cm[i] = Cm[tx + 16 * i];

        // ---- S = Q K^T : 4 rows x 4 scattered cols per thread ----
        float s[4][4];
        #pragma unroll
        for (int j = 0; j < 4; ++j)
            #pragma unroll
            for (int i = 0; i < 4; ++i) s[j][i] = 0.0f;

        #pragma unroll
        for (int d4 = 0; d4 < 16; ++d4) {
            float4 q[4];
            #pragma unroll
            for (int j = 0; j < 4; ++j)
                q[j] = *reinterpret_cast<const float4*>(&Qs[(4 * ty + j) * STRIDE + 4 * d4]);
            #pragma unroll
            for (int i = 0; i < 4; ++i) {
                float4 k4 = *reinterpret_cast<const float4*>(&Ks[(tx + 16 * i) * STRIDE + 4 * d4]);
                #pragma unroll
                for (int j = 0; j < 4; ++j) {
                    s[j][i] += q[j].x * k4.x + q[j].y * k4.y + q[j].z * k4.z + q[j].w * k4.w;
                }
            }
        }

        // ---- mask + online softmax (reduce over 16-lane tx group) ----
        float alpha[4];
        #pragma unroll
        for (int j = 0; j < 4; ++j) {
            float rmax = -INFINITY;
            #pragma unroll
            for (int i = 0; i < 4; ++i) {
                float x = (rm[j] | cm[i]) ? -1e10f : s[j][i];
                s[j][i] = x;
                rmax = fmaxf(rmax, x);
            }
            rmax = fmaxf(rmax, __shfl_xor_sync(0xffffffffu, rmax, 1));
            rmax = fmaxf(rmax, __shfl_xor_sync(0xffffffffu, rmax, 2));
            rmax = fmaxf(rmax, __shfl_xor_sync(0xffffffffu, rmax, 4));
            rmax = fmaxf(rmax, __shfl_xor_sync(0xffffffffu, rmax, 8));
            float mn = fmaxf(m_[j], rmax);
            alpha[j] = __expf(m_[j] - mn);
            float ps = 0.0f;
            #pragma unroll
            for (int i = 0; i < 4; ++i) {
                float p = __expf(s[j][i] - mn);
                s[j][i] = p;
                ps += p;
            }
            ps += __shfl_xor_sync(0xffffffffu, ps, 1);
            ps += __shfl_xor_sync(0xffffffffu, ps, 2);
            ps += __shfl_xor_sync(0xffffffffu, ps, 4);
            ps += __shfl_xor_sync(0xffffffffu, ps, 8);
            l_[j] = l_[j] * alpha[j] + ps;
            m_[j] = mn;
            #pragma unroll
            for (int c = 0; c < 4; ++c) oacc[j][c] *= alpha[j];
        }

        __syncthreads();  // all Ks reads done before Ps overwrites

        // ---- scatter P to smem (conflict-free) ----
        #pragma unroll
        for (int j = 0; j < 4; ++j)
            #pragma unroll
            for (int i = 0; i < 4; ++i)
                Ps[(4 * ty + j) * STRIDE + tx + 16 * i] = s[j][i];
        __syncthreads();

        // ---- O += P V : 4 rows x 4 contiguous d-cols per thread ----
        #pragma unroll
        for (int k4 = 0; k4 < 16; ++k4) {
            float4 p[4];
            #pragma unroll
            for (int j = 0; j < 4; ++j)
                p[j] = *reinterpret_cast<const float4*>(&Ps[(4 * ty + j) * STRIDE + 4 * k4]);
            #pragma unroll
            for (int kk = 0; kk < 4; ++kk) {
                float4 v4 = *reinterpret_cast<const float4*>(&Vs[(4 * k4 + kk) * STRIDE + 4 * tx]);
                #pragma unroll
                for (int j = 0; j < 4; ++j) {
                    float pj = (kk == 0) ? p[j].x : (kk == 1) ? p[j].y : (kk == 2) ? p[j].z : p[j].w;
                    oacc[j][0] += pj * v4.x;
                    oacc[j][1] += pj * v4.y;
                    oacc[j][2] += pj * v4.z;
                    oacc[j][3] += pj * v4.w;
                }
            }
        }
    }

    // ---- epilogue: normalize + coalesced store; O is (B,H,S,D) ----
    #pragma unroll
    for (int j = 0; j < 4; ++j) {
        float inv = 1.0f / l_[j];
        size_t row = (size_t)qt * TILE + 4 * ty + j;
        float* ob = O + (((size_t)b * H_ + h) * S_ + row) * D_ + 4 * tx;
        float4 o = make_float4(oacc[j][0] * inv, oacc[j][1] * inv,
                               oacc[j][2] * inv, oacc[j][3] * inv);
        *reinterpret_cast<float4*>(ob) = o;
    }
}

static const int SMEM_BYTES = (TILE * STRIDE * 3) * 4 + 64 * 4;  // 52480

extern "C" void kernel_launch(void* const* d_in, const int* in_sizes, int n_in,
                              void* d_out, int out_size) {
    const float* Q = (const float*)d_in[0];
    const float* K = (const float*)d_in[1];
    const float* V = (const float*)d_in[2];
    const int* qm_b = (const int*)d_in[3];
    const int* qm_s = (const int*)d_in[4];
    const int* km_b = (const int*)d_in[5];
    const int* km_s = (const int*)d_in[6];
    float* O = (float*)d_out;

    cudaFuncSetAttribute(attn_kernel, cudaFuncAttributeMaxDynamicSharedMemorySize, SMEM_BYTES);

    zero_masks_kernel<<<(B_ * S_ + 255) / 256, 256>>>();
    scatter_masks_kernel<<<(M_ + 255) / 256, 256>>>(qm_b, qm_s, km_b, km_s);
    attn_kernel<<<B_ * H_ * (S_ / TILE), THREADS, SMEM_BYTES>>>(Q, K, V, O);
}

// round 7
// speedup vs baseline: 14.5348x; 2.2653x over previous
#include <cuda_runtime.h>
#include <math.h>

#define B_ 8
#define S_ 1024
#define H_ 16
#define D_ 64
#define M_ 1024
#define HD (H_ * D_)

__device__ unsigned char g_rowmask[B_ * S_];
__device__ unsigned char g_colmask[B_ * S_];

__global__ void zero_masks_kernel() {
    int i = blockIdx.x * blockDim.x + threadIdx.x;
    if (i < B_ * S_) {
        g_rowmask[i] = 0;
        g_colmask[i] = 0;
    }
}

__global__ void scatter_masks_kernel(const int* __restrict__ qm_b, const int* __restrict__ qm_s,
                                     const int* __restrict__ km_b, const int* __restrict__ km_s) {
    int i = blockIdx.x * blockDim.x + threadIdx.x;
    if (i < M_) {
        g_rowmask[qm_b[i] * S_ + qm_s[i]] = 1;
        g_colmask[km_b[i] * S_ + km_s[i]] = 1;
    }
}

__device__ __forceinline__ unsigned f2tf(float x) {
    unsigned u;
    asm("cvt.rna.tf32.f32 %0, %1;" : "=r"(u) : "f"(x));
    return u;
}

__device__ __forceinline__ void mma8(float& c0, float& c1, float& c2, float& c3,
                                     unsigned a0, unsigned a1, unsigned a2, unsigned a3,
                                     unsigned b0, unsigned b1) {
    asm volatile(
        "mma.sync.aligned.m16n8k8.row.col.f32.tf32.tf32.f32 "
        "{%0,%1,%2,%3}, {%4,%5,%6,%7}, {%8,%9}, {%0,%1,%2,%3};"
        : "+f"(c0), "+f"(c1), "+f"(c2), "+f"(c3)
        : "r"(a0), "r"(a1), "r"(a2), "r"(a3), "r"(b0), "r"(b1));
}

// Flash attention on tensor cores (tf32 mma.sync).
// Grid: B*H*(S/128) = 1024 CTAs; 8 warps; warp w owns q-rows [w*16, w*16+16).
// Per warp: 16x64 S tile = 8 n-tiles x 8 k-steps of m16n8k8.
// Ks[seq][68]: B-frag read bank = 4*g+q = lane  -> conflict-free.
// Vt[d][68]  : transposed V, same conflict-free property for the PV B-frags.
__global__ __launch_bounds__(256, 2) void attn_kernel(const float* __restrict__ Q,
                                                      const float* __restrict__ K,
                                                      const float* __restrict__ V,
                                                      float* __restrict__ O) {
    __shared__ float Ks[64 * 68];
    __shared__ float Vt[64 * 68];
    __shared__ unsigned char CmB[64];

    const int bid = blockIdx.x;
    const int qt = bid & 7;
    const int h  = (bid >> 3) & 15;
    const int b  = bid >> 7;
    const int tid = threadIdx.x;
    const int w = tid >> 5, lane = tid & 31;
    const int g = lane >> 2, q = lane & 3;

    const int r0 = qt * 128 + w * 16 + g;  // global q-row for c0/c1; +8 for c2/c3

    // ---- Q fragments in registers (scale 1/8 folded, tf32-rounded) ----
    unsigned qf[8][4];
    {
        const float* Qb = Q + ((size_t)(b * S_ + r0)) * HD + h * D_;
        #pragma unroll
        for (int ks = 0; ks < 8; ++ks) {
            qf[ks][0] = f2tf(Qb[ks * 8 + q] * 0.125f);
            qf[ks][1] = f2tf(Qb[(size_t)8 * HD + ks * 8 + q] * 0.125f);
            qf[ks][2] = f2tf(Qb[ks * 8 + q + 4] * 0.125f);
            qf[ks][3] = f2tf(Qb[(size_t)8 * HD + ks * 8 + q + 4] * 0.125f);
        }
    }
    const int rm0 = g_rowmask[b * S_ + r0];
    const int rm1 = g_rowmask[b * S_ + r0 + 8];

    float o_[8][4];
    #pragma unroll
    for (int nt = 0; nt < 8; ++nt) { o_[nt][0] = o_[nt][1] = o_[nt][2] = o_[nt][3] = 0.f; }
    float m0 = -INFINITY, m1 = -INFINITY, l0 = 0.f, l1 = 0.f;

    const float* Kb = K + (size_t)b * S_ * HD + h * D_;
    const float* Vb = V + ((size_t)b * H_ + h) * S_ * D_;

    for (int kt = 0; kt < 16; ++kt) {
        __syncthreads();  // previous tile's smem fully consumed

        // ---- stage K (row-major) and V (transposed) tiles, tf32-rounded ----
        // s-major lane mapping: warp = 32 consecutive seq rows, c4 uniform ->
        // K STS.128 conflict-free, Vt scatter STS.32 conflict-free.
        #pragma unroll
        for (int t = 0; t < 4; ++t) {
            int idx = t * 256 + tid;
            int c4 = idx >> 6, s = idx & 63;
            float4 kk = *(const float4*)(Kb + (size_t)(kt * 64 + s) * HD + 4 * c4);
            uint4 kp;
            kp.x = f2tf(kk.x); kp.y = f2tf(kk.y); kp.z = f2tf(kk.z); kp.w = f2tf(kk.w);
            *(uint4*)&Ks[s * 68 + 4 * c4] = kp;
            float4 vv = *(const float4*)(Vb + (size_t)(kt * 64 + s) * D_ + 4 * c4);
            Vt[(4 * c4 + 0) * 68 + s] = __uint_as_float(f2tf(vv.x));
            Vt[(4 * c4 + 1) * 68 + s] = __uint_as_float(f2tf(vv.y));
            Vt[(4 * c4 + 2) * 68 + s] = __uint_as_float(f2tf(vv.z));
            Vt[(4 * c4 + 3) * 68 + s] = __uint_as_float(f2tf(vv.w));
        }
        if (tid < 64) CmB[tid] = g_colmask[b * S_ + kt * 64 + tid];
        __syncthreads();

        // ---- S = Q K^T (8 independent accumulator chains) ----
        float s_[8][4];
        #pragma unroll
        for (int nt = 0; nt < 8; ++nt) { s_[nt][0] = s_[nt][1] = s_[nt][2] = s_[nt][3] = 0.f; }

        #pragma unroll
        for (int ks = 0; ks < 8; ++ks) {
            #pragma unroll
            for (int nt = 0; nt < 8; ++nt) {
                const float* kp = &Ks[(nt * 8 + g) * 68 + ks * 8 + q];
                mma8(s_[nt][0], s_[nt][1], s_[nt][2], s_[nt][3],
                     qf[ks][0], qf[ks][1], qf[ks][2], qf[ks][3],
                     __float_as_uint(kp[0]), __float_as_uint(kp[4]));
            }
        }

        // ---- mask + online softmax (C layout: c0=(g,2q) c1=(g,2q+1) c2/c3=row g+8) ----
        float tm0 = -INFINITY, tm1 = -INFINITY;
        #pragma unroll
        for (int nt = 0; nt < 8; ++nt) {
            unsigned cc = *(const unsigned short*)(CmB + nt * 8 + 2 * q);
            int c0 = (int)(cc & 0xFFu), c1 = (int)(cc >> 8);
            if (rm0 | c0) s_[nt][0] = -1e10f;
            if (rm0 | c1) s_[nt][1] = -1e10f;
            if (rm1 | c0) s_[nt][2] = -1e10f;
            if (rm1 | c1) s_[nt][3] = -1e10f;
            tm0 = fmaxf(tm0, fmaxf(s_[nt][0], s_[nt][1]));
            tm1 = fmaxf(tm1, fmaxf(s_[nt][2], s_[nt][3]));
        }
        tm0 = fmaxf(tm0, __shfl_xor_sync(0xffffffffu, tm0, 1));
        tm0 = fmaxf(tm0, __shfl_xor_sync(0xffffffffu, tm0, 2));
        tm1 = fmaxf(tm1, __shfl_xor_sync(0xffffffffu, tm1, 1));
        tm1 = fmaxf(tm1, __shfl_xor_sync(0xffffffffu, tm1, 2));
        float mn0 = fmaxf(m0, tm0), mn1 = fmaxf(m1, tm1);
        float al0 = __expf(m0 - mn0), al1 = __expf(m1 - mn1);
        float ps0 = 0.f, ps1 = 0.f;
        #pragma unroll
        for (int nt = 0; nt < 8; ++nt) {
            s_[nt][0] = __expf(s_[nt][0] - mn0);
            s_[nt][1] = __expf(s_[nt][1] - mn0);
            s_[nt][2] = __expf(s_[nt][2] - mn1);
            s_[nt][3] = __expf(s_[nt][3] - mn1);
            ps0 += s_[nt][0] + s_[nt][1];
            ps1 += s_[nt][2] + s_[nt][3];
        }
        ps0 += __shfl_xor_sync(0xffffffffu, ps0, 1);
        ps0 += __shfl_xor_sync(0xffffffffu, ps0, 2);
        ps1 += __shfl_xor_sync(0xffffffffu, ps1, 1);
        ps1 += __shfl_xor_sync(0xffffffffu, ps1, 2);
        l0 = l0 * al0 + ps0;
        l1 = l1 * al1 + ps1;
        m0 = mn0; m1 = mn1;
        #pragma unroll
        for (int nt = 0; nt < 8; ++nt) {
            o_[nt][0] *= al0; o_[nt][1] *= al0; o_[nt][2] *= al1; o_[nt][3] *= al1;
        }

        // ---- C-frag -> A-frag relayout of P via shuffles (in place), tf32-rounded ----
        // want a0=(g,q) a1=(g+8,q) a2=(g,q+4) a3=(g+8,q+4); col c held by lane
        // (base|c>>1) slot c&1.
        const int base = lane & ~3;
        const int src_lo = base | (q >> 1);
        const int src_hi = src_lo + 2;
        #pragma unroll
        for (int ks = 0; ks < 8; ++ks) {
            float t0 = __shfl_sync(0xffffffffu, s_[ks][0], src_lo);
            float t1 = __shfl_sync(0xffffffffu, s_[ks][1], src_lo);
            float u0 = __shfl_sync(0xffffffffu, s_[ks][2], src_lo);
            float u1 = __shfl_sync(0xffffffffu, s_[ks][3], src_lo);
            float v0 = __shfl_sync(0xffffffffu, s_[ks][0], src_hi);
            float v1 = __shfl_sync(0xffffffffu, s_[ks][1], src_hi);
            float x0 = __shfl_sync(0xffffffffu, s_[ks][2], src_hi);
            float x1 = __shfl_sync(0xffffffffu, s_[ks][3], src_hi);
            s_[ks][0] = __uint_as_float(f2tf((q & 1) ? t1 : t0));
            s_[ks][1] = __uint_as_float(f2tf((q & 1) ? u1 : u0));
            s_[ks][2] = __uint_as_float(f2tf((q & 1) ? v1 : v0));
            s_[ks][3] = __uint_as_float(f2tf((q & 1) ? x1 : x0));
        }

        // ---- O += P V ----
        #pragma unroll
        for (int ks = 0; ks < 8; ++ks) {
            #pragma unroll
            for (int nt = 0; nt < 8; ++nt) {
                const float* vp = &Vt[(nt * 8 + g) * 68 + ks * 8 + q];
                mma8(o_[nt][0], o_[nt][1], o_[nt][2], o_[nt][3],
                     __float_as_uint(s_[ks][0]), __float_as_uint(s_[ks][1]),
                     __float_as_uint(s_[ks][2]), __float_as_uint(s_[ks][3]),
                     __float_as_uint(vp[0]), __float_as_uint(vp[4]));
            }
        }
    }

    // ---- epilogue: normalize + store; O is (B,H,S,D) ----
    const float il0 = 1.f / l0, il1 = 1.f / l1;
    float* Ob = O + (((size_t)b * H_ + h) * S_ + r0) * D_;
    #pragma unroll
    for (int nt = 0; nt < 8; ++nt) {
        *(float2*)(Ob + nt * 8 + 2 * q) = make_float2(o_[nt][0] * il0, o_[nt][1] * il0);
        *(float2*)(Ob + (size_t)8 * D_ + nt * 8 + 2 * q) = make_float2(o_[nt][2] * il1, o_[nt][3] * il1);
    }
}

extern "C" void kernel_launch(void* const* d_in, const int* in_sizes, int n_in,
                              void* d_out, int out_size) {
    const float* Q = (const float*)d_in[0];
    const float* K = (const float*)d_in[1];
    const float* V = (const float*)d_in[2];
    const int* qm_b = (const int*)d_in[3];
    const int* qm_s = (const int*)d_in[4];
    const int* km_b = (const int*)d_in[5];
    const int* km_s = (const int*)d_in[6];
    float* O = (float*)d_out;

    zero_masks_kernel<<<(B_ * S_ + 255) / 256, 256>>>();
    scatter_masks_kernel<<<(M_ + 255) / 256, 256>>>(qm_b, qm_s, km_b, km_s);
    attn_kernel<<<B_ * H_ * (S_ / 128), 256>>>(Q, K, V, O);
}

// round 8
// speedup vs baseline: 16.1238x; 1.1093x over previous
#include <cuda_runtime.h>
#include <math.h>

#define B_ 8
#define S_ 1024
#define H_ 16
#define D_ 64
#define M_ 1024
#define HD (H_ * D_)

#define KSTR 68  // K smem stride: B-frag bank = 4g+q  -> conflict-free
#define VSTR 72  // V smem stride: B-frag bank = 8q+g  -> conflict-free
#define PSTR 68  // P smem stride: A-frag bank = 4g+q  -> conflict-free

__device__ unsigned char g_rowmask[B_ * S_];
__device__ unsigned char g_colmask[B_ * S_];

__global__ void zero_masks_kernel() {
    int i = blockIdx.x * blockDim.x + threadIdx.x;
    if (i < B_ * S_) {
        g_rowmask[i] = 0;
        g_colmask[i] = 0;
    }
}

__global__ void scatter_masks_kernel(const int* __restrict__ qm_b, const int* __restrict__ qm_s,
                                     const int* __restrict__ km_b, const int* __restrict__ km_s) {
    int i = blockIdx.x * blockDim.x + threadIdx.x;
    if (i < M_) {
        g_rowmask[qm_b[i] * S_ + qm_s[i]] = 1;
        g_colmask[km_b[i] * S_ + km_s[i]] = 1;
    }
}

__device__ __forceinline__ unsigned f2tf(float x) {
    unsigned u;
    asm("cvt.rna.tf32.f32 %0, %1;" : "=r"(u) : "f"(x));
    return u;
}

__device__ __forceinline__ void mma8(float& c0, float& c1, float& c2, float& c3,
                                     unsigned a0, unsigned a1, unsigned a2, unsigned a3,
                                     unsigned b0, unsigned b1) {
    asm volatile(
        "mma.sync.aligned.m16n8k8.row.col.f32.tf32.tf32.f32 "
        "{%0,%1,%2,%3}, {%4,%5,%6,%7}, {%8,%9}, {%0,%1,%2,%3};"
        : "+f"(c0), "+f"(c1), "+f"(c2), "+f"(c3)
        : "r"(a0), "r"(a1), "r"(a2), "r"(a3), "r"(b0), "r"(b1));
}

// Flash attention, tf32 mma.sync, 32-row warp tiles.
// Grid: B*H*(S/128) = 1024 CTAs; 128 threads = 4 warps; warp w owns q-rows
// [w*32, w*32+32) as two m16 row-tiles. B-frags (K and V) loaded once per
// (nt,ks) and reused by both row-tiles. P relayout via warp-private smem.
__global__ __launch_bounds__(128, 2) void attn_kernel(const float* __restrict__ Q,
                                                      const float* __restrict__ K,
                                                      const float* __restrict__ V,
                                                      float* __restrict__ O) {
    extern __shared__ float smem[];
    float* Ks = smem;                       // 64 * KSTR
    float* Vs = Ks + 64 * KSTR;             // 64 * VSTR
    float* Ps = Vs + 64 * VSTR;             // 4 warps * 32 * PSTR
    unsigned char* CmB = (unsigned char*)(Ps + 4 * 32 * PSTR);  // 64

    const int bid = blockIdx.x;
    const int qt = bid & 7;
    const int h  = (bid >> 3) & 15;
    const int b  = bid >> 7;
    const int tid = threadIdx.x;
    const int w = tid >> 5, lane = tid & 31;
    const int g = lane >> 2, q = lane & 3;

    float* Pw = Ps + w * (32 * PSTR);       // warp-private P buffer
    const int row0 = qt * 128 + w * 32;     // CTA-global q-row base of this warp

    // ---- Q fragments for both row-tiles (scale 1/8 folded, tf32 RNA) ----
    unsigned qf[2][8][4];
    {
        #pragma unroll
        for (int t = 0; t < 2; ++t) {
            const float* Qb = Q + ((size_t)(b * S_ + row0 + 16 * t + g)) * HD + h * D_;
            #pragma unroll
            for (int ks = 0; ks < 8; ++ks) {
                qf[t][ks][0] = f2tf(Qb[ks * 8 + q] * 0.125f);
                qf[t][ks][1] = f2tf(Qb[(size_t)8 * HD + ks * 8 + q] * 0.125f);
                qf[t][ks][2] = f2tf(Qb[ks * 8 + q + 4] * 0.125f);
                qf[t][ks][3] = f2tf(Qb[(size_t)8 * HD + ks * 8 + q + 4] * 0.125f);
            }
        }
    }
    int rm[2][2];
    #pragma unroll
    for (int t = 0; t < 2; ++t) {
        rm[t][0] = g_rowmask[b * S_ + row0 + 16 * t + g];
        rm[t][1] = g_rowmask[b * S_ + row0 + 16 * t + g + 8];
    }

    float o_[2][8][4];
    #pragma unroll
    for (int t = 0; t < 2; ++t)
        #pragma unroll
        for (int nt = 0; nt < 8; ++nt)
            o_[t][nt][0] = o_[t][nt][1] = o_[t][nt][2] = o_[t][nt][3] = 0.f;
    float m_[2][2], l_[2][2];
    #pragma unroll
    for (int t = 0; t < 2; ++t) { m_[t][0] = m_[t][1] = -INFINITY; l_[t][0] = l_[t][1] = 0.f; }

    const float* Kb = K + (size_t)b * S_ * HD + h * D_;
    const float* Vb = V + ((size_t)b * H_ + h) * S_ * D_;

    for (int kt = 0; kt < 16; ++kt) {
        __syncthreads();  // previous tile's Ks/Vs fully consumed

        // ---- stage K (stride 68) and V (stride 72), both row-major, tf32 RNA ----
        #pragma unroll
        for (int i = 0; i < 8; ++i) {
            int idx = i * 128 + tid;
            int c4 = idx >> 6, s = idx & 63;
            float4 kk = *(const float4*)(Kb + (size_t)(kt * 64 + s) * HD + 4 * c4);
            uint4 kp;
            kp.x = f2tf(kk.x); kp.y = f2tf(kk.y); kp.z = f2tf(kk.z); kp.w = f2tf(kk.w);
            *(uint4*)&Ks[s * KSTR + 4 * c4] = kp;
        }
        #pragma unroll
        for (int i = 0; i < 8; ++i) {
            int idx = i * 128 + tid;
            int c4 = idx >> 6, s = idx & 63;
            float4 vv = *(const float4*)(Vb + (size_t)(kt * 64 + s) * D_ + 4 * c4);
            uint4 vp;
            vp.x = f2tf(vv.x); vp.y = f2tf(vv.y); vp.z = f2tf(vv.z); vp.w = f2tf(vv.w);
            *(uint4*)&Vs[s * VSTR + 4 * c4] = vp;
        }
        if (tid < 64) CmB[tid] = g_colmask[b * S_ + kt * 64 + tid];
        __syncthreads();

        // ---- S = Q K^T : B-frags shared by both row-tiles ----
        float s0[8][4], s1[8][4];
        #pragma unroll
        for (int nt = 0; nt < 8; ++nt) {
            s0[nt][0] = s0[nt][1] = s0[nt][2] = s0[nt][3] = 0.f;
            s1[nt][0] = s1[nt][1] = s1[nt][2] = s1[nt][3] = 0.f;
        }
        #pragma unroll
        for (int ks = 0; ks < 8; ++ks) {
            #pragma unroll
            for (int nt = 0; nt < 8; ++nt) {
                const float* kp = &Ks[(nt * 8 + g) * KSTR + ks * 8 + q];
                unsigned b0 = __float_as_uint(kp[0]);
                unsigned b1 = __float_as_uint(kp[4]);
                mma8(s0[nt][0], s0[nt][1], s0[nt][2], s0[nt][3],
                     qf[0][ks][0], qf[0][ks][1], qf[0][ks][2], qf[0][ks][3], b0, b1);
                mma8(s1[nt][0], s1[nt][1], s1[nt][2], s1[nt][3],
                     qf[1][ks][0], qf[1][ks][1], qf[1][ks][2], qf[1][ks][3], b0, b1);
            }
        }

        // ---- mask + online softmax ----
        float al[2][2];
        #pragma unroll
        for (int t = 0; t < 2; ++t) {
            float (*s_)[4] = t ? s1 : s0;
            float tm0 = -INFINITY, tm1 = -INFINITY;
            #pragma unroll
            for (int nt = 0; nt < 8; ++nt) {
                unsigned cc = *(const unsigned short*)(CmB + nt * 8 + 2 * q);
                int c0 = (int)(cc & 0xFFu), c1 = (int)(cc >> 8);
                if (rm[t][0] | c0) s_[nt][0] = -1e10f;
                if (rm[t][0] | c1) s_[nt][1] = -1e10f;
                if (rm[t][1] | c0) s_[nt][2] = -1e10f;
                if (rm[t][1] | c1) s_[nt][3] = -1e10f;
                tm0 = fmaxf(tm0, fmaxf(s_[nt][0], s_[nt][1]));
                tm1 = fmaxf(tm1, fmaxf(s_[nt][2], s_[nt][3]));
            }
            tm0 = fmaxf(tm0, __shfl_xor_sync(0xffffffffu, tm0, 1));
            tm0 = fmaxf(tm0, __shfl_xor_sync(0xffffffffu, tm0, 2));
            tm1 = fmaxf(tm1, __shfl_xor_sync(0xffffffffu, tm1, 1));
            tm1 = fmaxf(tm1, __shfl_xor_sync(0xffffffffu, tm1, 2));
            float mn0 = fmaxf(m_[t][0], tm0), mn1 = fmaxf(m_[t][1], tm1);
            float a0 = __expf(m_[t][0] - mn0), a1 = __expf(m_[t][1] - mn1);
            float ps0 = 0.f, ps1 = 0.f;
            #pragma unroll
            for (int nt = 0; nt < 8; ++nt) {
                s_[nt][0] = __expf(s_[nt][0] - mn0);
                s_[nt][1] = __expf(s_[nt][1] - mn0);
                s_[nt][2] = __expf(s_[nt][2] - mn1);
                s_[nt][3] = __expf(s_[nt][3] - mn1);
                ps0 += s_[nt][0] + s_[nt][1];
                ps1 += s_[nt][2] + s_[nt][3];
            }
            ps0 += __shfl_xor_sync(0xffffffffu, ps0, 1);
            ps0 += __shfl_xor_sync(0xffffffffu, ps0, 2);
            ps1 += __shfl_xor_sync(0xffffffffu, ps1, 1);
            ps1 += __shfl_xor_sync(0xffffffffu, ps1, 2);
            l_[t][0] = l_[t][0] * a0 + ps0;
            l_[t][1] = l_[t][1] * a1 + ps1;
            m_[t][0] = mn0; m_[t][1] = mn1;
            al[t][0] = a0; al[t][1] = a1;
        }
        #pragma unroll
        for (int t = 0; t < 2; ++t)
            #pragma unroll
            for (int nt = 0; nt < 8; ++nt) {
                o_[t][nt][0] *= al[t][0]; o_[t][nt][1] *= al[t][0];
                o_[t][nt][2] *= al[t][1]; o_[t][nt][3] *= al[t][1];
            }

        // ---- P -> warp-private smem (tf32 RNA), then consume as A-frags ----
        __syncwarp();  // prior PV reads of Pw done (lanes may skew)
        #pragma unroll
        for (int t = 0; t < 2; ++t) {
            float (*s_)[4] = t ? s1 : s0;
            #pragma unroll
            for (int nt = 0; nt < 8; ++nt) {
                uint2 lo = make_uint2(f2tf(s_[nt][0]), f2tf(s_[nt][1]));
                uint2 hi = make_uint2(f2tf(s_[nt][2]), f2tf(s_[nt][3]));
                *(uint2*)&Pw[(16 * t + g) * PSTR + 8 * nt + 2 * q] = lo;
                *(uint2*)&Pw[(16 * t + g + 8) * PSTR + 8 * nt + 2 * q] = hi;
            }
        }
        __syncwarp();

        // ---- O += P V ----
        #pragma unroll
        for (int ks = 0; ks < 8; ++ks) {
            unsigned a[2][4];
            #pragma unroll
            for (int t = 0; t < 2; ++t) {
                const float* pp = &Pw[(16 * t + g) * PSTR + 8 * ks + q];
                a[t][0] = __float_as_uint(pp[0]);
                a[t][1] = __float_as_uint(pp[8 * PSTR]);
                a[t][2] = __float_as_uint(pp[4]);
                a[t][3] = __float_as_uint(pp[8 * PSTR + 4]);
            }
            #pragma unroll
            for (int nt = 0; nt < 8; ++nt) {
                const float* vp = &Vs[(ks * 8 + q) * VSTR + 8 * nt + g];
                unsigned b0 = __float_as_uint(vp[0]);
                unsigned b1 = __float_as_uint(vp[4 * VSTR]);
                mma8(o_[0][nt][0], o_[0][nt][1], o_[0][nt][2], o_[0][nt][3],
                     a[0][0], a[0][1], a[0][2], a[0][3], b0, b1);
                mma8(o_[1][nt][0], o_[1][nt][1], o_[1][nt][2], o_[1][nt][3],
                     a[1][0], a[1][1], a[1][2], a[1][3], b0, b1);
            }
        }
    }

    // ---- epilogue: normalize + store; O is (B,H,S,D) ----
    float* Ob = O + (((size_t)b * H_ + h) * S_ + row0) * D_;
    #pragma unroll
    for (int t = 0; t < 2; ++t) {
        float il0 = 1.f / l_[t][0], il1 = 1.f / l_[t][1];
        float* r_lo = Ob + (size_t)(16 * t + g) * D_;
        float* r_hi = Ob + (size_t)(16 * t + g + 8) * D_;
        #pragma unroll
        for (int nt = 0; nt < 8; ++nt) {
            *(float2*)(r_lo + 8 * nt + 2 * q) =
                make_float2(o_[t][nt][0] * il0, o_[t][nt][1] * il0);
            *(float2*)(r_hi + 8 * nt + 2 * q) =
                make_float2(o_[t][nt][2] * il1, o_[t][nt][3] * il1);
        }
    }
}

static const int SMEM_BYTES = (64 * KSTR + 64 * VSTR + 4 * 32 * PSTR) * 4 + 64;

extern "C" void kernel_launch(void* const* d_in, const int* in_sizes, int n_in,
                              void* d_out, int out_size) {
    const float* Q = (const float*)d_in[0];
    const float* K = (const float*)d_in[1];
    const float* V = (const float*)d_in[2];
    const int* qm_b = (const int*)d_in[3];
    const int* qm_s = (const int*)d_in[4];
    const int* km_b = (const int*)d_in[5];
    const int* km_s = (const int*)d_in[6];
    float* O = (float*)d_out;

    cudaFuncSetAttribute(attn_kernel, cudaFuncAttributeMaxDynamicSharedMemorySize, SMEM_BYTES);

    zero_masks_kernel<<<(B_ * S_ + 255) / 256, 256>>>();
    scatter_masks_kernel<<<(M_ + 255) / 256, 256>>>(qm_b, qm_s, km_b, km_s);
    attn_kernel<<<B_ * H_ * (S_ / 128), 128, SMEM_BYTES>>>(Q, K, V, O);
}